// round 2
// baseline (speedup 1.0000x reference)
#include <cuda_runtime.h>

#define SQ   4096
#define BHN  64
#define PB   68     // plain smem pitch (floats)
#define PD   132    // duplicated smem pitch (floats), rows of 128 data floats
#define NSPLIT 16

typedef unsigned long long u64t;

// ---------------- scratch ----------------
__device__ float g_Qlmd[BHN*64*128];   // pooled Q landmarks, *0.125, duplicated pairs
__device__ float g_KlmT[BHN*64*64];    // pooled K landmarks, transposed [d][lm]
__device__ float g_Invd[BHN*64*128];   // Newton inverse, duplicated pairs
__device__ float g_W   [BHN*64*64];    // inv @ F
__device__ float g_pacc[(size_t)NSPLIT*BHN*64*64];
__device__ float g_pmax[NSPLIT*BHN*64];
__device__ float g_psum[NSPLIT*BHN*64];

// ---------------- packed f32x2 helpers ----------------
__device__ __forceinline__ u64t pk2(float lo, float hi) {
    u64t r; asm("mov.b64 %0, {%1, %2};" : "=l"(r) : "f"(lo), "f"(hi)); return r;
}
__device__ __forceinline__ void unpk2(u64t v, float& lo, float& hi) {
    asm("mov.b64 {%0, %1}, %2;" : "=f"(lo), "=f"(hi) : "l"(v));
}
__device__ __forceinline__ u64t ffma2(u64t a, u64t b, u64t c) {
    u64t d; asm("fma.rn.f32x2 %0, %1, %2, %3;" : "=l"(d) : "l"(a), "l"(b), "l"(c)); return d;
}
__device__ __forceinline__ u64t fmul2(u64t a, u64t b) {
    u64t d; asm("mul.rn.f32x2 %0, %1, %2;" : "=l"(d) : "l"(a), "l"(b)); return d;
}

// ---------------- dup-A 64x64x64 matmul core ----------------
// C[i][j] = sum_k A[i][k]*B[k][j]; A duplicated (pitch PD), B plain (pitch PB)
// thread: rows {rq,rq+16,rq+32,rq+48}, cols 4cq..4cq+3
__device__ __forceinline__ void mmd_core(const float* __restrict__ Ad,
                                         const float* __restrict__ Bp,
                                         int rq, int cq, u64t acc[4][2]) {
#pragma unroll
    for (int k = 0; k < 64; k += 2) {
        ulonglong2 b0 = *reinterpret_cast<const ulonglong2*>(Bp + k*PB + 4*cq);
        ulonglong2 b1 = *reinterpret_cast<const ulonglong2*>(Bp + (k+1)*PB + 4*cq);
#pragma unroll
        for (int r = 0; r < 4; r++) {
            ulonglong2 a = *reinterpret_cast<const ulonglong2*>(Ad + (rq+16*r)*PD + 2*k);
            acc[r][0] = ffma2(a.x, b0.x, acc[r][0]);
            acc[r][1] = ffma2(a.x, b0.y, acc[r][1]);
            acc[r][0] = ffma2(a.y, b1.x, acc[r][0]);
            acc[r][1] = ffma2(a.y, b1.y, acc[r][1]);
        }
    }
}

// write one thread's 4x4 tile into a duplicated-layout matrix
__device__ __forceinline__ void dup_store(float* Cd, int rq, int cq,
                                          const u64t acc[4][2]) {
#pragma unroll
    for (int r = 0; r < 4; r++) {
        float v0, v1, v2, v3;
        unpk2(acc[r][0], v0, v1);
        unpk2(acc[r][1], v2, v3);
        u64t* p = (u64t*)(Cd + (rq+16*r)*PD + 8*cq);
        p[0] = pk2(v0, v0); p[1] = pk2(v1, v1);
        p[2] = pk2(v2, v2); p[3] = pk2(v3, v3);
    }
}

// ---------------- plain-A matmul (Newton chain only; latency-hidden) ----------------
__device__ __noinline__ void mm64_p(const float* __restrict__ A,
                                    const float* __restrict__ B,
                                    float* __restrict__ C, int tid) {
    int cq = tid & 15, rq = tid >> 4;
    u64t acc[4][2] = {};
#pragma unroll
    for (int k = 0; k < 64; k++) {
        u64t b0 = *(const u64t*)(B + k*PB + 4*cq);
        u64t b1 = *(const u64t*)(B + k*PB + 4*cq + 2);
#pragma unroll
        for (int r = 0; r < 4; r++) {
            float a = A[(rq+16*r)*PB + k];
            u64t a2 = pk2(a, a);
            acc[r][0] = ffma2(a2, b0, acc[r][0]);
            acc[r][1] = ffma2(a2, b1, acc[r][1]);
        }
    }
#pragma unroll
    for (int r = 0; r < 4; r++) {
        *(u64t*)(C + (rq+16*r)*PB + 4*cq)     = acc[r][0];
        *(u64t*)(C + (rq+16*r)*PB + 4*cq + 2) = acc[r][1];
    }
}

// ---------------- pooling ----------------
__global__ void __launch_bounds__(256) pool_kernel(const float* __restrict__ Q,
                                                   const float* __restrict__ K) {
    int bh = blockIdx.x >> 6, lm = blockIdx.x & 63;
    int d = threadIdx.x & 63, rg = threadIdx.x >> 6;
    const float* qb = Q + ((size_t)bh*SQ + lm*64)*64 + d;
    const float* kb = K + ((size_t)bh*SQ + lm*64)*64 + d;
    float sq = 0.f, sk = 0.f;
    for (int r = rg; r < 64; r += 4) { sq += qb[(size_t)r*64]; sk += kb[(size_t)r*64]; }
    __shared__ float shq[256], shk[256];
    shq[threadIdx.x] = sq; shk[threadIdx.x] = sk;
    __syncthreads();
    if (rg == 0) {
        float q = (shq[d] + shq[64+d] + shq[128+d] + shq[192+d]) * (1.0f/512.0f); // mean * 0.125
        float k = (shk[d] + shk[64+d] + shk[128+d] + shk[192+d]) * (1.0f/64.0f);
        *(u64t*)(g_Qlmd + (size_t)(bh*64 + lm)*128 + 2*d) = pk2(q, q);
        g_KlmT[bh*4096 + d*64 + lm] = k;
    }
}

// ---------------- Newton-Schulz inverse body (64 blocks inside mega) ----------------
__device__ void newton_body(float* sm, int bh) {
    float* A  = sm;
    float* Vb = sm + 1*64*PB;
    float* P  = sm + 2*64*PB;
    float* T  = sm + 3*64*PB;
    float* U  = sm + 4*64*PB;
    __shared__ float nsred[256], nsrow[64], nscol[64], nscale[1];
    int tid = threadIdx.x;

    for (int idx = tid; idx < 4096; idx += 256) {
        int i = idx >> 6, k = idx & 63;
        T[i*PB + k] = g_Qlmd[(size_t)bh*8192 + i*128 + 2*k];   // already *0.125
        U[k*PB + i] = g_KlmT[bh*4096 + k*64 + i];              // wait: direct copy below
    }
    // fix U layout: g_KlmT is [d][lm]; we want U[d*PB + lm]
    __syncthreads();
    for (int idx = tid; idx < 4096; idx += 256) {
        int dd = idx >> 6, lm = idx & 63;
        U[dd*PB + lm] = g_KlmT[bh*4096 + dd*64 + lm];
    }
    __syncthreads();
    mm64_p(T, U, A, tid);          // A = 0.125 * Qlm Klm^T
    __syncthreads();
    {   // row softmax of A
        int q = tid & 3, r = tid >> 2;
        float* Lr = A + r*PB + q*16;
        float mt = Lr[0];
#pragma unroll
        for (int c = 1; c < 16; c++) mt = fmaxf(mt, Lr[c]);
        nsred[tid] = mt; __syncthreads();
        float m = fmaxf(fmaxf(nsred[r*4], nsred[r*4+1]), fmaxf(nsred[r*4+2], nsred[r*4+3]));
        float ps = 0.f;
#pragma unroll
        for (int c = 0; c < 16; c++) { float e = __expf(Lr[c] - m); Lr[c] = e; ps += e; }
        __syncthreads();
        nsred[tid] = ps; __syncthreads();
        float inv = 1.0f / (nsred[r*4] + nsred[r*4+1] + nsred[r*4+2] + nsred[r*4+3]);
#pragma unroll
        for (int c = 0; c < 16; c++) Lr[c] *= inv;
    }
    __syncthreads();
    if (tid < 64)       { float s = 0.f; for (int j = 0; j < 64; j++) s += A[tid*PB + j]; nsrow[tid] = s; }
    else if (tid < 128) { int c = tid - 64; float s = 0.f; for (int i = 0; i < 64; i++) s += A[i*PB + c]; nscol[c] = s; }
    __syncthreads();
    if (tid == 0) {
        float mr = nsrow[0], mc = nscol[0];
        for (int i = 1; i < 64; i++) { mr = fmaxf(mr, nsrow[i]); mc = fmaxf(mc, nscol[i]); }
        nscale[0] = 1.0f / (mr * mc);
    }
    __syncthreads();
    float sc = nscale[0];
    for (int idx = tid; idx < 4096; idx += 256) {
        int i = idx >> 6, j = idx & 63;
        Vb[j*PB + i] = A[i*PB + j] * sc;
    }
    __syncthreads();
#pragma unroll 1
    for (int it = 0; it < 6; it++) {
        mm64_p(A, Vb, P, tid); __syncthreads();
        for (int idx = tid; idx < 4096; idx += 256) {
            int i = idx >> 6, j = idx & 63;
            T[i*PB + j] = (i == j ? 7.0f : 0.0f) - P[i*PB + j];
        }
        __syncthreads();
        mm64_p(P, T, U, tid); __syncthreads();
        for (int idx = tid; idx < 4096; idx += 256) {
            int i = idx >> 6, j = idx & 63;
            T[i*PB + j] = (i == j ? 15.0f : 0.0f) - U[i*PB + j];
        }
        __syncthreads();
        mm64_p(P, T, U, tid); __syncthreads();
        for (int idx = tid; idx < 4096; idx += 256) {
            int i = idx >> 6, j = idx & 63;
            T[i*PB + j] = (i == j ? 3.25f : 0.0f) - 0.25f * U[i*PB + j];
        }
        __syncthreads();
        mm64_p(Vb, T, U, tid); __syncthreads();
        float* tmp = Vb; Vb = U; U = tmp;
    }
    // store inverse duplicated
    for (int idx = tid; idx < 4096; idx += 256) {
        int i = idx >> 6, j = idx & 63;
        float v = Vb[i*PB + j];
        *(u64t*)(g_Invd + (size_t)bh*8192 + i*128 + 2*j) = pk2(v, v);
    }
}

// ---------------- kc body (split flash over S): F-partials ----------------
__device__ void kc_body(const float* __restrict__ K, const float* __restrict__ V,
                        float* sm, int sp, int bh) {
    float* Qsd = sm;                       // 64*PD dup
    float* KtT = sm + 64*PD;               // 64*PB
    float* Vt  = sm + 64*PD + 64*PB;       // 64*PB
    float* Ld  = sm + 64*PD + 2*64*PB;     // 64*PD dup
    __shared__ float sred[256], rmax[64], rsum[64], rfac[64];
    int tid = threadIdx.x;

    for (int idx = tid; idx < 2048; idx += 256)
        *(float4*)(Qsd + (idx>>5)*PD + ((idx&31)<<2)) =
            *(const float4*)(g_Qlmd + (size_t)bh*8192 + (idx<<2));
    if (tid < 64) { rmax[tid] = -1e30f; rsum[tid] = 0.0f; }
    int cq = tid & 15, rq = tid >> 4;
    int q = tid & 3,  r  = tid >> 2;
    u64t acc[4][2] = {};
    __syncthreads();

#pragma unroll 1
    for (int t = 0; t < 4; t++) {
        int s0 = sp*256 + t*64;
#pragma unroll
        for (int itld = 0; itld < 4; itld++) {
            int f4 = tid + itld*256;
            int j = f4 >> 4, k4 = (f4 & 15) << 2;
            float4 kv = *(const float4*)(K + ((size_t)bh*SQ + s0 + j)*64 + k4);
            KtT[(k4+0)*PB + j] = kv.x; KtT[(k4+1)*PB + j] = kv.y;
            KtT[(k4+2)*PB + j] = kv.z; KtT[(k4+3)*PB + j] = kv.w;
            float4 vv = *(const float4*)(V + ((size_t)bh*SQ + s0 + j)*64 + k4);
            *(float4*)(Vt + j*PB + k4) = vv;
        }
        __syncthreads();
        u64t lacc[4][2] = {};
        mmd_core(Qsd, KtT, rq, cq, lacc);
        dup_store(Ld, rq, cq, lacc);
        __syncthreads();
        // online softmax (4 threads per row; dup layout: value at base[2c])
        float* base = Ld + r*PD + (q << 5);
        float mt = base[0];
#pragma unroll
        for (int c = 1; c < 16; c++) mt = fmaxf(mt, base[2*c]);
        sred[tid] = mt; __syncthreads();
        if (q == 0) {
            float m4 = fmaxf(fmaxf(sred[tid], sred[tid+1]), fmaxf(sred[tid+2], sred[tid+3]));
            float nm = fmaxf(rmax[r], m4);
            rfac[r] = __expf(rmax[r] - nm);
            rmax[r] = nm;
        }
        __syncthreads();
        float nm = rmax[r], ps = 0.f;
#pragma unroll
        for (int c = 0; c < 16; c++) {
            float e = __expf(base[2*c] - nm);
            *(u64t*)(base + 2*c) = pk2(e, e);
            ps += e;
        }
        sred[tid] = ps; __syncthreads();
        if (q == 0) rsum[r] = rsum[r]*rfac[r] + sred[tid]+sred[tid+1]+sred[tid+2]+sred[tid+3];
        __syncthreads();
#pragma unroll
        for (int rr = 0; rr < 4; rr++) {
            float f = rfac[rq + 16*rr];
            u64t f2 = pk2(f, f);
            acc[rr][0] = fmul2(acc[rr][0], f2);
            acc[rr][1] = fmul2(acc[rr][1], f2);
        }
        mmd_core(Ld, Vt, rq, cq, acc);
        __syncthreads();
    }
    size_t base2 = ((size_t)sp*BHN + bh)*4096;
#pragma unroll
    for (int rr = 0; rr < 4; rr++) {
        ulonglong2 st; st.x = acc[rr][0]; st.y = acc[rr][1];
        *(ulonglong2*)(g_pacc + base2 + (rq+16*rr)*64 + 4*cq) = st;
    }
    if (tid < 64) {
        g_pmax[(sp*BHN+bh)*64 + tid] = rmax[tid];
        g_psum[(sp*BHN+bh)*64 + tid] = rsum[tid];
    }
}

// ---------------- mega: newton (blocks 0..63) + kc (blocks 64..1087) ----------------
__global__ void __launch_bounds__(256, 2) mega_kernel(const float* __restrict__ K,
                                                      const float* __restrict__ V) {
    extern __shared__ float sm[];
    if (blockIdx.x < 64) {
        newton_body(sm, blockIdx.x);
    } else {
        int id = blockIdx.x - 64;
        kc_body(K, V, sm, id & (NSPLIT-1), id >> 4);
    }
}

// ---------------- reduce splits -> F, then W = Inv @ F ----------------
__global__ void __launch_bounds__(256) reduce_winv_kernel() {
    extern __shared__ float sm[];
    float* Fs   = sm;               // 64*PB plain
    float* Invd = sm + 64*PB;       // 64*PD dup
    int bh = blockIdx.x, tid = threadIdx.x;

    for (int idx = tid; idx < 2048; idx += 256)
        *(float4*)(Invd + (idx>>5)*PD + ((idx&31)<<2)) =
            *(const float4*)(g_Invd + (size_t)bh*8192 + (idx<<2));

    int d = tid & 63, ig = tid >> 6;
    for (int i = ig; i < 64; i += 4) {
        float gm = -1e30f;
#pragma unroll
        for (int s = 0; s < NSPLIT; s++) gm = fmaxf(gm, g_pmax[(s*BHN+bh)*64 + i]);
        float tot = 0.f, w[NSPLIT];
#pragma unroll
        for (int s = 0; s < NSPLIT; s++) {
            w[s] = __expf(g_pmax[(s*BHN+bh)*64 + i] - gm);
            tot += g_psum[(s*BHN+bh)*64 + i] * w[s];
        }
        float v = 0.f;
#pragma unroll
        for (int s = 0; s < NSPLIT; s++)
            v += g_pacc[((size_t)s*BHN+bh)*4096 + i*64 + d] * w[s];
        Fs[i*PB + d] = v / tot;
    }
    __syncthreads();
    int cq = tid & 15, rq = tid >> 4;
    u64t acc[4][2] = {};
    mmd_core(Invd, Fs, rq, cq, acc);
#pragma unroll
    for (int rr = 0; rr < 4; rr++) {
        ulonglong2 st; st.x = acc[rr][0]; st.y = acc[rr][1];
        *(ulonglong2*)(g_W + (size_t)bh*4096 + (rq+16*rr)*64 + 4*cq) = st;
    }
}

// ---------------- kd: X = softmax(0.125 Q Klm^T) @ W ----------------
__global__ void __launch_bounds__(256, 2) kd_kernel(const float* __restrict__ Q,
                                                    float* __restrict__ X) {
    extern __shared__ float sm[];
    float* Qtd = sm;                     // 64*PD dup
    float* Ld  = sm + 64*PD;             // 64*PD dup
    float* Wsp = sm + 2*64*PD;           // 64*PB
    float* KlT = sm + 2*64*PD + 64*PB;   // 64*PB
    __shared__ float sred[256], rinv[64];
    int tid = threadIdx.x;
    int ch = blockIdx.x, bh = blockIdx.y;

    for (int idx = tid; idx < 1024; idx += 256) {
        *(float4*)(Wsp + (idx>>4)*PB + ((idx&15)<<2)) =
            *(const float4*)(g_W + (size_t)bh*4096 + (idx<<2));
        *(float4*)(KlT + (idx>>4)*PB + ((idx&15)<<2)) =
            *(const float4*)(g_KlmT + (size_t)bh*4096 + (idx<<2));
    }
    int cq = tid & 15, rq = tid >> 4;
    int q = tid & 3,  r  = tid >> 2;
    __syncthreads();

#pragma unroll 1
    for (int t = 0; t < 4; t++) {
        int s0 = ch*256 + t*64;
#pragma unroll
        for (int itld = 0; itld < 4; itld++) {
            int f4 = tid + itld*256;
            int j = f4 >> 4, k4 = (f4 & 15) << 2;
            float4 qv = *(const float4*)(Q + ((size_t)bh*SQ + s0 + j)*64 + k4);
            u64t* p = (u64t*)(Qtd + j*PD + 2*k4);
            p[0] = pk2(qv.x*0.125f, qv.x*0.125f);
            p[1] = pk2(qv.y*0.125f, qv.y*0.125f);
            p[2] = pk2(qv.z*0.125f, qv.z*0.125f);
            p[3] = pk2(qv.w*0.125f, qv.w*0.125f);
        }
        __syncthreads();
        u64t lacc[4][2] = {};
        mmd_core(Qtd, KlT, rq, cq, lacc);
        dup_store(Ld, rq, cq, lacc);
        __syncthreads();
        float* base = Ld + r*PD + (q << 5);
        float mt = base[0];
#pragma unroll
        for (int c = 1; c < 16; c++) mt = fmaxf(mt, base[2*c]);
        sred[tid] = mt; __syncthreads();
        float m = fmaxf(fmaxf(sred[r*4], sred[r*4+1]), fmaxf(sred[r*4+2], sred[r*4+3]));
        float ps = 0.f;
#pragma unroll
        for (int c = 0; c < 16; c++) {
            float e = __expf(base[2*c] - m);
            *(u64t*)(base + 2*c) = pk2(e, e);
            ps += e;
        }
        sred[tid] = ps; __syncthreads();
        if (q == 0) rinv[r] = 1.0f / (sred[tid]+sred[tid+1]+sred[tid+2]+sred[tid+3]);
        __syncthreads();
        u64t acc[4][2] = {};
        mmd_core(Ld, Wsp, rq, cq, acc);
#pragma unroll
        for (int rr = 0; rr < 4; rr++) {
            float f = rinv[rq + 16*rr];
            u64t f2 = pk2(f, f);
            ulonglong2 o; o.x = fmul2(acc[rr][0], f2); o.y = fmul2(acc[rr][1], f2);
            *(ulonglong2*)(X + ((size_t)bh*SQ + s0 + rq + 16*rr)*64 + 4*cq) = o;
        }
        __syncthreads();
    }
}

// ---------------- launcher ----------------
extern "C" void kernel_launch(void* const* d_in, const int* in_sizes, int n_in,
                              void* d_out, int out_size) {
    (void)in_sizes; (void)n_in; (void)out_size;
    const float* Q = (const float*)d_in[0];
    const float* K = (const float*)d_in[1];
    const float* V = (const float*)d_in[2];
    float* X = (float*)d_out;

    const int SMEM_MEGA = (2*64*PD + 2*64*PB) * 4;   // 102400 B
    const int SMEM_RW   = (64*PD + 64*PB) * 4;       // 51200 B
    cudaFuncSetAttribute(mega_kernel,        cudaFuncAttributeMaxDynamicSharedMemorySize, SMEM_MEGA);
    cudaFuncSetAttribute(kd_kernel,          cudaFuncAttributeMaxDynamicSharedMemorySize, SMEM_MEGA);
    cudaFuncSetAttribute(reduce_winv_kernel, cudaFuncAttributeMaxDynamicSharedMemorySize, SMEM_RW);

    pool_kernel<<<BHN*64, 256>>>(Q, K);
    mega_kernel<<<64 + NSPLIT*BHN, 256, SMEM_MEGA>>>(K, V);
    reduce_winv_kernel<<<BHN, 256, SMEM_RW>>>();
    kd_kernel<<<dim3(16, BHN), 256, SMEM_MEGA>>>(Q, X);
}

// round 4
// speedup vs baseline: 1.3813x; 1.3813x over previous
#include <cuda_runtime.h>
#include <cstdint>

#define SQ   4096
#define BHN  64
#define PB   68
#define NSPLIT 16

typedef unsigned long long u64t;

// ---------------- scratch ----------------
__device__ float g_Qlm [BHN*64*64];   // landmark means of Q, *0.125 folded
__device__ float g_KlmT[BHN*64*64];   // landmark means of K, [d][lm]
__device__ float g_Klm [BHN*64*64];   // landmark means of K, [lm][d]
__device__ float g_Inv [BHN*64*64];   // Newton inverse
__device__ float g_W   [BHN*64*64];   // inv @ F : [m][d]
__device__ float g_pacc[(size_t)NSPLIT*BHN*64*64];
__device__ float g_pmax[NSPLIT*BHN*64];
__device__ float g_psum[NSPLIT*BHN*64];

// ---------------- f32x2 helpers ----------------
__device__ __forceinline__ u64t pk2(float lo, float hi) {
    u64t r; asm("mov.b64 %0, {%1, %2};" : "=l"(r) : "f"(lo), "f"(hi)); return r;
}
__device__ __forceinline__ u64t ffma2(u64t a, u64t b, u64t c) {
    u64t d; asm("fma.rn.f32x2 %0, %1, %2, %3;" : "=l"(d) : "l"(a), "l"(b), "l"(c)); return d;
}
__device__ __forceinline__ u64t fmul2(u64t a, u64t b) {
    u64t d; asm("mul.rn.f32x2 %0, %1, %2;" : "=l"(d) : "l"(a), "l"(b)); return d;
}
__device__ __forceinline__ float tf32r(float x) {
    float r; asm("cvt.rna.tf32.f32 %0, %1;" : "=f"(r) : "f"(x)); return r;
}

// ---------------- mma.sync m16n8k8 tf32 ----------------
__device__ __forceinline__ void mma8(float c[4], float a0, float a1, float a2, float a3,
                                     float b0, float b1) {
    asm volatile("mma.sync.aligned.m16n8k8.row.col.f32.tf32.tf32.f32 "
        "{%0,%1,%2,%3}, {%4,%5,%6,%7}, {%8,%9}, {%0,%1,%2,%3};"
        : "+f"(c[0]), "+f"(c[1]), "+f"(c[2]), "+f"(c[3])
        : "r"(__float_as_uint(a0)), "r"(__float_as_uint(a1)),
          "r"(__float_as_uint(a2)), "r"(__float_as_uint(a3)),
          "r"(__float_as_uint(b0)), "r"(__float_as_uint(b1)));
}

// ---------------- plain 64x64x64 smem matmul (R1-proven) ----------------
__device__ __forceinline__ void mm64_core(const float* __restrict__ A,
                                          const float* __restrict__ B,
                                          int rq, int cq, u64t acc[4][2]) {
#pragma unroll
    for (int k = 0; k < 64; k++) {
        u64t b0 = *(const u64t*)(B + k*PB + 2*cq);
        u64t b1 = *(const u64t*)(B + k*PB + 2*cq + 32);
#pragma unroll
        for (int r = 0; r < 4; r++) {
            float a = A[(rq + 16*r)*PB + k];
            u64t a2 = pk2(a, a);
            acc[r][0] = ffma2(a2, b0, acc[r][0]);
            acc[r][1] = ffma2(a2, b1, acc[r][1]);
        }
    }
}
__device__ __noinline__ void mm64_smem(const float* __restrict__ A,
                                       const float* __restrict__ B,
                                       float* __restrict__ C, int tid) {
    int cq = tid & 15, rq = tid >> 4;
    u64t acc[4][2] = {};
    mm64_core(A, B, rq, cq, acc);
#pragma unroll
    for (int r = 0; r < 4; r++) {
        *(u64t*)(C + (rq+16*r)*PB + 2*cq)      = acc[r][0];
        *(u64t*)(C + (rq+16*r)*PB + 2*cq + 32) = acc[r][1];
    }
}

// ---------------- pooling ----------------
__global__ void __launch_bounds__(256) pool_kernel(const float* __restrict__ Q,
                                                   const float* __restrict__ K) {
    int bh = blockIdx.x >> 6, lm = blockIdx.x & 63;
    int d = threadIdx.x & 63, rg = threadIdx.x >> 6;
    const float* qb = Q + ((size_t)bh*SQ + lm*64)*64 + d;
    const float* kb = K + ((size_t)bh*SQ + lm*64)*64 + d;
    float sq = 0.f, sk = 0.f;
    for (int r = rg; r < 64; r += 4) { sq += qb[(size_t)r*64]; sk += kb[(size_t)r*64]; }
    __shared__ float shq[256], shk[256];
    shq[threadIdx.x] = sq; shk[threadIdx.x] = sk;
    __syncthreads();
    if (rg == 0) {
        float q = (shq[d] + shq[64+d] + shq[128+d] + shq[192+d]) * (1.0f/512.0f); // mean*0.125
        float k = (shk[d] + shk[64+d] + shk[128+d] + shk[192+d]) * (1.0f/64.0f);
        g_Qlm [bh*4096 + lm*64 + d] = q;
        g_Klm [bh*4096 + lm*64 + d] = k;
        g_KlmT[bh*4096 + d*64 + lm] = k;
    }
}

// ---------------- Newton-Schulz body ----------------
__device__ void newton_body(float* sm, int bh) {
    float* A  = sm;
    float* Vb = sm + 1*64*PB;
    float* P  = sm + 2*64*PB;
    float* T  = sm + 3*64*PB;
    float* U  = sm + 4*64*PB;
    __shared__ float nsred[256], nsrow[64], nscol[64], nscale[1];
    int tid = threadIdx.x;

    for (int idx = tid; idx < 4096; idx += 256) {
        int i = idx >> 6, k = idx & 63;
        T[i*PB + k] = g_Qlm[bh*4096 + idx];
        U[i*PB + k] = g_KlmT[bh*4096 + idx];
    }
    __syncthreads();
    mm64_smem(T, U, A, tid);
    __syncthreads();
    {
        int q = tid & 3, r = tid >> 2;
        float* Lr = A + r*PB + q*16;
        float mt = Lr[0];
#pragma unroll
        for (int c = 1; c < 16; c++) mt = fmaxf(mt, Lr[c]);
        nsred[tid] = mt; __syncthreads();
        float m = fmaxf(fmaxf(nsred[r*4], nsred[r*4+1]), fmaxf(nsred[r*4+2], nsred[r*4+3]));
        float ps = 0.f;
#pragma unroll
        for (int c = 0; c < 16; c++) { float e = __expf(Lr[c] - m); Lr[c] = e; ps += e; }
        __syncthreads();
        nsred[tid] = ps; __syncthreads();
        float inv = 1.0f / (nsred[r*4] + nsred[r*4+1] + nsred[r*4+2] + nsred[r*4+3]);
#pragma unroll
        for (int c = 0; c < 16; c++) Lr[c] *= inv;
    }
    __syncthreads();
    if (tid < 64)       { float s = 0.f; for (int j = 0; j < 64; j++) s += A[tid*PB + j]; nsrow[tid] = s; }
    else if (tid < 128) { int c = tid - 64; float s = 0.f; for (int i = 0; i < 64; i++) s += A[i*PB + c]; nscol[c] = s; }
    __syncthreads();
    if (tid == 0) {
        float mr = nsrow[0], mc = nscol[0];
        for (int i = 1; i < 64; i++) { mr = fmaxf(mr, nsrow[i]); mc = fmaxf(mc, nscol[i]); }
        nscale[0] = 1.0f / (mr * mc);
    }
    __syncthreads();
    float sc = nscale[0];
    for (int idx = tid; idx < 4096; idx += 256) {
        int i = idx >> 6, j = idx & 63;
        Vb[j*PB + i] = A[i*PB + j] * sc;
    }
    __syncthreads();
#pragma unroll 1
    for (int it = 0; it < 6; it++) {
        mm64_smem(A, Vb, P, tid); __syncthreads();
        for (int idx = tid; idx < 4096; idx += 256) {
            int i = idx >> 6, j = idx & 63;
            T[i*PB + j] = (i == j ? 7.0f : 0.0f) - P[i*PB + j];
        }
        __syncthreads();
        mm64_smem(P, T, U, tid); __syncthreads();
        for (int idx = tid; idx < 4096; idx += 256) {
            int i = idx >> 6, j = idx & 63;
            T[i*PB + j] = (i == j ? 15.0f : 0.0f) - U[i*PB + j];
        }
        __syncthreads();
        mm64_smem(P, T, U, tid); __syncthreads();
        for (int idx = tid; idx < 4096; idx += 256) {
            int i = idx >> 6, j = idx & 63;
            T[i*PB + j] = (i == j ? 3.25f : 0.0f) - 0.25f * U[i*PB + j];
        }
        __syncthreads();
        mm64_smem(Vb, T, U, tid); __syncthreads();
        float* tmp = Vb; Vb = U; U = tmp;
    }
    for (int idx = tid; idx < 4096; idx += 256) {
        int i = idx >> 6, j = idx & 63;
        g_Inv[bh*4096 + idx] = Vb[i*PB + j];
    }
}

// ---------------- kc body (flash split over S) ----------------
__device__ void kc_body(const float* __restrict__ K, const float* __restrict__ V,
                        float* sm, int sp, int bh) {
    float* Qs  = sm;
    float* KtT = sm + 64*PB;
    float* Vt  = sm + 2*64*PB;
    float* L   = sm + 3*64*PB;
    __shared__ float sred[256], rmax[64], rsum[64], rfac[64];
    int tid = threadIdx.x;

    for (int idx = tid; idx < 4096; idx += 256) {
        int i = idx >> 6, k = idx & 63;
        Qs[i*PB + k] = g_Qlm[bh*4096 + idx];
    }
    if (tid < 64) { rmax[tid] = -1e30f; rsum[tid] = 0.0f; }
    u64t acc[4][2] = {};
    int cq = tid & 15, rq = tid >> 4;
    int q = tid & 3,  r  = tid >> 2;
    __syncthreads();

#pragma unroll 1
    for (int t = 0; t < 4; t++) {
        int s0 = sp*256 + t*64;
#pragma unroll
        for (int itld = 0; itld < 4; itld++) {
            int f4 = tid + itld*256;
            int j = f4 >> 4, k4 = (f4 & 15) << 2;
            float4 kv = *(const float4*)(K + ((size_t)bh*SQ + s0 + j)*64 + k4);
            KtT[(k4+0)*PB + j] = kv.x; KtT[(k4+1)*PB + j] = kv.y;
            KtT[(k4+2)*PB + j] = kv.z; KtT[(k4+3)*PB + j] = kv.w;
            float4 vv = *(const float4*)(V + ((size_t)bh*SQ + s0 + j)*64 + k4);
            *(float4*)(Vt + j*PB + k4) = vv;
        }
        __syncthreads();
        mm64_smem(Qs, KtT, L, tid);
        __syncthreads();
        float* Lr = L + r*PB + q*16;
        float mt = Lr[0];
#pragma unroll
        for (int c = 1; c < 16; c++) mt = fmaxf(mt, Lr[c]);
        sred[tid] = mt; __syncthreads();
        if (q == 0) {
            float m4 = fmaxf(fmaxf(sred[tid], sred[tid+1]), fmaxf(sred[tid+2], sred[tid+3]));
            float nm = fmaxf(rmax[r], m4);
            rfac[r] = __expf(rmax[r] - nm);
            rmax[r] = nm;
        }
        __syncthreads();
        float nm = rmax[r], ps = 0.f;
#pragma unroll
        for (int c = 0; c < 16; c++) { float e = __expf(Lr[c] - nm); Lr[c] = e; ps += e; }
        __syncthreads();
        sred[tid] = ps; __syncthreads();
        if (q == 0) rsum[r] = rsum[r]*rfac[r] + sred[tid]+sred[tid+1]+sred[tid+2]+sred[tid+3];
        __syncthreads();
#pragma unroll
        for (int rr = 0; rr < 4; rr++) {
            float f = rfac[rq + 16*rr];
            u64t f2 = pk2(f, f);
            acc[rr][0] = fmul2(acc[rr][0], f2);
            acc[rr][1] = fmul2(acc[rr][1], f2);
        }
        mm64_core(L, Vt, rq, cq, acc);
        __syncthreads();
    }
    size_t base = ((size_t)sp*BHN + bh)*4096;
#pragma unroll
    for (int rr = 0; rr < 4; rr++) {
        *(u64t*)(g_pacc + base + (rq+16*rr)*64 + 2*cq)      = acc[rr][0];
        *(u64t*)(g_pacc + base + (rq+16*rr)*64 + 2*cq + 32) = acc[rr][1];
    }
    if (tid < 64) {
        g_pmax[(sp*BHN+bh)*64 + tid] = rmax[tid];
        g_psum[(sp*BHN+bh)*64 + tid] = rsum[tid];
    }
}

__global__ void __launch_bounds__(256, 2) mega_kernel(const float* __restrict__ K,
                                                      const float* __restrict__ V) {
    extern __shared__ float smg[];
    if (blockIdx.x < 64) newton_body(smg, blockIdx.x);
    else { int id = blockIdx.x - 64; kc_body(K, V, smg, id & (NSPLIT-1), id >> 4); }
}

// ---------------- reduce splits -> F, W = Inv@F ----------------
__global__ void __launch_bounds__(256) reduce_winv_kernel() {
    extern __shared__ float smr[];
    float* Fs = smr;
    float* Iv = smr + 64*PB;
    int bh = blockIdx.x, tid = threadIdx.x;

    for (int idx = tid; idx < 4096; idx += 256)
        Iv[(idx>>6)*PB + (idx&63)] = g_Inv[bh*4096 + idx];

    int d = tid & 63, ig = tid >> 6;
    for (int i = ig; i < 64; i += 4) {
        float gm = -1e30f;
#pragma unroll
        for (int s = 0; s < NSPLIT; s++) gm = fmaxf(gm, g_pmax[(s*BHN+bh)*64 + i]);
        float tot = 0.f, w[NSPLIT];
#pragma unroll
        for (int s = 0; s < NSPLIT; s++) {
            w[s] = __expf(g_pmax[(s*BHN+bh)*64 + i] - gm);
            tot += g_psum[(s*BHN+bh)*64 + i] * w[s];
        }
        float v = 0.f;
#pragma unroll
        for (int s = 0; s < NSPLIT; s++)
            v += g_pacc[((size_t)s*BHN+bh)*4096 + i*64 + d] * w[s];
        Fs[i*PB + d] = v / tot;
    }
    __syncthreads();
    int cq = tid & 15, rq = tid >> 4;
    u64t acc[4][2] = {};
    mm64_core(Iv, Fs, rq, cq, acc);
#pragma unroll
    for (int rr = 0; rr < 4; rr++) {
        *(u64t*)(g_W + (size_t)bh*4096 + (rq+16*rr)*64 + 2*cq)      = acc[rr][0];
        *(u64t*)(g_W + (size_t)bh*4096 + (rq+16*rr)*64 + 2*cq + 32) = acc[rr][1];
    }
}

// ---------------- kd: mma.sync tf32 3x, X = softmax(0.125 Q Klm^T) @ W ----------------
__global__ void __launch_bounds__(256, 1) kd_mma(const float* __restrict__ Q,
                                                 float* __restrict__ X) {
    extern __shared__ float sk[];
    float* QH = sk;                 // 128 x pitch68 (later reused for P hi)
    float* QL = QH + 128*PB;        // 128 x pitch68 (later P lo)
    float* KH = QL + 128*PB;        // 64 x pitch68
    float* KL = KH + 64*PB;
    float* WH = KL + 64*PB;
    float* WL = WH + 64*PB;
    int tid = threadIdx.x, lane = tid & 31, wid = tid >> 5;
    int g = lane >> 2, t = lane & 3;
    int tile = blockIdx.x, bh = blockIdx.y;

    // ---- load Q tile (128x64), scale, hi/lo split ----
    const float* q0 = Q + ((size_t)bh*SQ + tile*128)*64;
#pragma unroll
    for (int it = 0; it < 8; it++) {
        int f4 = it*256 + tid;
        int r = f4 >> 4, c4 = (f4 & 15) << 2;
        float4 v = *(const float4*)(q0 + r*64 + c4);
        v.x *= 0.125f; v.y *= 0.125f; v.z *= 0.125f; v.w *= 0.125f;
        float4 h, l;
        h.x = tf32r(v.x); l.x = v.x - h.x;
        h.y = tf32r(v.y); l.y = v.y - h.y;
        h.z = tf32r(v.z); l.z = v.z - h.z;
        h.w = tf32r(v.w); l.w = v.w - h.w;
        *(float4*)(QH + r*PB + c4) = h;
        *(float4*)(QL + r*PB + c4) = l;
    }
    // ---- load Klm and W (64x64 each), hi/lo split ----
    const float* kl0 = g_Klm + (size_t)bh*4096;
    const float* w0  = g_W   + (size_t)bh*4096;
#pragma unroll
    for (int it = 0; it < 4; it++) {
        int f4 = it*256 + tid;
        int r = f4 >> 4, c4 = (f4 & 15) << 2;
        float4 v = *(const float4*)(kl0 + r*64 + c4);
        float4 h, l;
        h.x = tf32r(v.x); l.x = v.x - h.x;
        h.y = tf32r(v.y); l.y = v.y - h.y;
        h.z = tf32r(v.z); l.z = v.z - h.z;
        h.w = tf32r(v.w); l.w = v.w - h.w;
        *(float4*)(KH + r*PB + c4) = h;
        *(float4*)(KL + r*PB + c4) = l;
        float4 w = *(const float4*)(w0 + r*64 + c4);
        float4 wh, wl;
        wh.x = tf32r(w.x); wl.x = w.x - wh.x;
        wh.y = tf32r(w.y); wl.y = w.y - wh.y;
        wh.z = tf32r(w.z); wl.z = w.z - wh.z;
        wh.w = tf32r(w.w); wl.w = w.w - wh.w;
        *(float4*)(WH + r*PB + c4) = wh;
        *(float4*)(WL + r*PB + c4) = wl;
    }
    __syncthreads();

    int rA = wid*16 + g;     // this thread's two logit rows within block tile
    int rB = rA + 8;
    float c[8][4];
#pragma unroll
    for (int n = 0; n < 8; n++) { c[n][0]=0.f; c[n][1]=0.f; c[n][2]=0.f; c[n][3]=0.f; }

    // ---- matmul1: logits = Qs @ Klm^T ; B[k][n] = Klm[n][k] ----
#pragma unroll
    for (int kt = 0; kt < 8; kt++) {
        int k0 = kt*8;
        float ah0 = QH[rA*PB + k0 + t],     ah1 = QH[rB*PB + k0 + t];
        float ah2 = QH[rA*PB + k0 + t + 4], ah3 = QH[rB*PB + k0 + t + 4];
        float al0 = QL[rA*PB + k0 + t],     al1 = QL[rB*PB + k0 + t];
        float al2 = QL[rA*PB + k0 + t + 4], al3 = QL[rB*PB + k0 + t + 4];
#pragma unroll
        for (int nt = 0; nt < 8; nt++) {
            int n0 = nt*8;
            float bh0 = KH[(n0+g)*PB + k0 + t], bh1 = KH[(n0+g)*PB + k0 + t + 4];
            float bl0 = KL[(n0+g)*PB + k0 + t], bl1 = KL[(n0+g)*PB + k0 + t + 4];
            mma8(c[nt], ah0, ah1, ah2, ah3, bh0, bh1);
            mma8(c[nt], al0, al1, al2, al3, bh0, bh1);
            mma8(c[nt], ah0, ah1, ah2, ah3, bl0, bl1);
        }
    }

    // ---- softmax over the 64 cols of rows rA, rB ----
    float mA = -1e30f, mB = -1e30f;
#pragma unroll
    for (int n = 0; n < 8; n++) {
        mA = fmaxf(mA, fmaxf(c[n][0], c[n][1]));
        mB = fmaxf(mB, fmaxf(c[n][2], c[n][3]));
    }
    mA = fmaxf(mA, __shfl_xor_sync(0xffffffffu, mA, 1));
    mA = fmaxf(mA, __shfl_xor_sync(0xffffffffu, mA, 2));
    mB = fmaxf(mB, __shfl_xor_sync(0xffffffffu, mB, 1));
    mB = fmaxf(mB, __shfl_xor_sync(0xffffffffu, mB, 2));
    float sA = 0.f, sB = 0.f;
#pragma unroll
    for (int n = 0; n < 8; n++) {
        c[n][0] = __expf(c[n][0] - mA); c[n][1] = __expf(c[n][1] - mA);
        c[n][2] = __expf(c[n][2] - mB); c[n][3] = __expf(c[n][3] - mB);
        sA += c[n][0] + c[n][1];
        sB += c[n][2] + c[n][3];
    }
    sA += __shfl_xor_sync(0xffffffffu, sA, 1);
    sA += __shfl_xor_sync(0xffffffffu, sA, 2);
    sB += __shfl_xor_sync(0xffffffffu, sB, 1);
    sB += __shfl_xor_sync(0xffffffffu, sB, 2);
    float rinvA = 1.0f / sA, rinvB = 1.0f / sB;

    // ---- store P hi/lo into Q buffers (warp-local rows; Q consumed) ----
#pragma unroll
    for (int n = 0; n < 8; n++) {
        int col = n*8 + 2*t;
        float h0 = tf32r(c[n][0]), h1 = tf32r(c[n][1]);
        float h2 = tf32r(c[n][2]), h3 = tf32r(c[n][3]);
        float2 ph0 = {h0, h1}, pl0 = {c[n][0]-h0, c[n][1]-h1};
        float2 ph1 = {h2, h3}, pl1 = {c[n][2]-h2, c[n][3]-h3};
        *(float2*)(QH + rA*PB + col) = ph0;
        *(float2*)(QL + rA*PB + col) = pl0;
        *(float2*)(QH + rB*PB + col) = ph1;
        *(float2*)(QL + rB*PB + col) = pl1;
    }
    __syncwarp();

    // ---- matmul2: X~ = P @ W ; B[k][n] = W[k][n] ----
#pragma unroll
    for (int n = 0; n < 8; n++) { c[n][0]=0.f; c[n][1]=0.f; c[n][2]=0.f; c[n][3]=0.f; }
#pragma unroll
    for (int kt = 0; kt < 8; kt++) {
        int k0 = kt*8;
        float ah0 = QH[rA*PB + k0 + t],     ah1 = QH[rB*PB + k0 + t];
        float ah2 = QH[rA*PB + k0 + t + 4], ah3 = QH[rB*PB + k0 + t + 4];
        float al0 = QL[rA*PB + k0 + t],     al1 = QL[rB*PB + k0 + t];
        float al2 = QL[rA*PB + k0 + t + 4], al3 = QL[rB*PB + k0 + t + 4];
#pragma unroll
        for (int nt = 0; nt < 8; nt++) {
            int n0 = nt*8;
            float bh0 = WH[(k0+t)*PB + n0 + g], bh1 = WH[(k0+t+4)*PB + n0 + g];
            float bl0 = WL[(k0+t)*PB + n0 + g], bl1 = WL[(k0+t+4)*PB + n0 + g];
            mma8(c[nt], ah0, ah1, ah2, ah3, bh0, bh1);
            mma8(c[nt], al0, al1, al2, al3, bh0, bh1);
            mma8(c[nt], ah0, ah1, ah2, ah3, bl0, bl1);
        }
    }

    // ---- normalize + store X ----
    float* x0 = X + ((size_t)bh*SQ + tile*128)*64;
#pragma unroll
    for (int n = 0; n < 8; n++) {
        int col = n*8 + 2*t;
        float2 o0 = {c[n][0]*rinvA, c[n][1]*rinvA};
        float2 o1 = {c[n][2]*rinvB, c[n][3]*rinvB};
        *(float2*)(x0 + rA*64 + col) = o0;
        *(float2*)(x0 + rB*64 + col) = o1;
    }
}

// ---------------- launcher ----------------
extern "C" void kernel_launch(void* const* d_in, const int* in_sizes, int n_in,
                              void* d_out, int out_size) {
    (void)in_sizes; (void)n_in; (void)out_size;
    const float* Q = (const float*)d_in[0];
    const float* K = (const float*)d_in[1];
    const float* V = (const float*)d_in[2];
    float* X = (float*)d_out;

    const int SMEM_MEGA = 5*64*PB*4;                  // 87040
    const int SMEM_RW   = 2*64*PB*4;                  // 34816
    const int SMEM_KD   = (2*128*PB + 4*64*PB)*4;     // 139264
    cudaFuncSetAttribute(mega_kernel,        cudaFuncAttributeMaxDynamicSharedMemorySize, SMEM_MEGA);
    cudaFuncSetAttribute(reduce_winv_kernel, cudaFuncAttributeMaxDynamicSharedMemorySize, SMEM_RW);
    cudaFuncSetAttribute(kd_mma,             cudaFuncAttributeMaxDynamicSharedMemorySize, SMEM_KD);

    pool_kernel<<<BHN*64, 256>>>(Q, K);
    mega_kernel<<<64 + NSPLIT*BHN, 256, SMEM_MEGA>>>(K, V);
    reduce_winv_kernel<<<BHN, 256, SMEM_RW>>>();
    kd_mma<<<dim3(32, BHN), 256, SMEM_KD>>>(Q, X);
}